// round 3
// baseline (speedup 1.0000x reference)
#include <cuda_runtime.h>

// LSTMModel: 2-layer LSTM (B=4096, T=256, D=4, H=64) + FC(64->1).
// Strategy: batch-parallel persistent-step kernels.
//   - kernel0: layer-0 LSTM, input projection fused (D=4), writes h1 to scratch.
//   - kernel1: layer-1 LSTM + final FC fused at last timestep.
// Thread t of a 256-thread CTA computes gate row t (i,f,g,o order) for NB=4
// batch elements, with weight rows in registers and h broadcast from smem.
// Inner product uses Blackwell packed fma.rn.f32x2 (2x fp32 throughput),
// packed along K so operands are natural aligned register pairs (no MOVs).

#define B_TOTAL 4096
#define T_STEPS 256
#define D_IN    4
#define HDIM    64
#define GDIM    256   // 4*H
#define NB      4     // batch elements per block

typedef unsigned long long u64;

// 268 MB scratch for h1 (layer0 output). Static device global: allowed.
__device__ float g_h1[(size_t)B_TOTAL * T_STEPS * HDIM];

__device__ __forceinline__ u64 pk(float lo, float hi) {
    u64 r; asm("mov.b64 %0,{%1,%2};" : "=l"(r) : "f"(lo), "f"(hi)); return r;
}
__device__ __forceinline__ void upk(u64 v, float& lo, float& hi) {
    asm("mov.b64 {%0,%1},%2;" : "=f"(lo), "=f"(hi) : "l"(v));
}
// d = a*b + c, lanewise on packed f32 pairs (Blackwell FFMA2)
__device__ __forceinline__ u64 f2(u64 a, u64 b, u64 c) {
    u64 d; asm("fma.rn.f32x2 %0,%1,%2,%3;" : "=l"(d) : "l"(a), "l"(b), "l"(c));
    return d;
}
__device__ __forceinline__ float sigf(float x) {
    return 1.0f / (1.0f + __expf(-x));
}

// ---------------------------------------------------------------------------
// Layer 0: x[B,T,4] -> h1[B,T,64]
// ---------------------------------------------------------------------------
__global__ void __launch_bounds__(256) lstm_layer0(
    const float* __restrict__ x, const float* __restrict__ Wih,
    const float* __restrict__ Whh, const float* __restrict__ bih,
    const float* __restrict__ bhh)
{
    __shared__ float x_sm[NB][T_STEPS * D_IN];  // 16 KB, e-major
    __shared__ float h_sm[NB][HDIM];            // 1 KB,  e-major
    __shared__ float g_sm[NB][GDIM];            // 4 KB,  e-major

    const int tid = threadIdx.x;
    const int b0  = blockIdx.x * NB;

    // Weight rows for gate `tid` into registers (as packed K-pairs).
    u64 wih[2];
    u64 whh[32];
    {
        const ulonglong2* wr = (const ulonglong2*)(Wih + tid * D_IN);
        ulonglong2 t = wr[0];
        wih[0] = t.x; wih[1] = t.y;
        const ulonglong2* hr = (const ulonglong2*)(Whh + tid * HDIM);
#pragma unroll
        for (int i = 0; i < 16; i++) {
            ulonglong2 v = hr[i];
            whh[2 * i] = v.x; whh[2 * i + 1] = v.y;
        }
    }
    const float bias = bih[tid] + bhh[tid];

    // Preload all x for this block's 4 batch elements (coalesced, once).
    for (int idx = tid; idx < NB * T_STEPS; idx += 256) {
        int e = idx >> 8;          // /256
        int r = idx & 255;
        ((float4*)x_sm[e])[r] =
            ((const float4*)(x + (size_t)(b0 + e) * T_STEPS * D_IN))[r];
    }
    ((float*)h_sm)[tid] = 0.0f;    // NB*H == 256 == blockDim
    float c_state = 0.0f;
    const int e_up = tid >> 6, j_up = tid & 63;
    float* h1_row = g_h1 + ((size_t)(b0 + e_up) * T_STEPS) * HDIM + j_up;
    __syncthreads();

    for (int s = 0; s < T_STEPS; s++) {
        // ---- gate pre-activation: thread computes row `tid` for all NB elems
        u64 acc[NB];
#pragma unroll
        for (int e = 0; e < NB; e++) {
            u64 a = pk(bias, 0.0f);
            ulonglong2 xv = *((const ulonglong2*)&x_sm[e][s * D_IN]);
            a = f2(xv.x, wih[0], a);
            a = f2(xv.y, wih[1], a);
            const ulonglong2* he = (const ulonglong2*)h_sm[e];
#pragma unroll
            for (int i = 0; i < 16; i++) {
                ulonglong2 hv = he[i];
                a = f2(hv.x, whh[2 * i], a);
                a = f2(hv.y, whh[2 * i + 1], a);
            }
            acc[e] = a;
        }
#pragma unroll
        for (int e = 0; e < NB; e++) {
            float lo, hi; upk(acc[e], lo, hi);
            g_sm[e][tid] = lo + hi;
        }
        __syncthreads();

        // ---- cell/hidden update: thread = one (elem, hidden) pair
        float gi = g_sm[e_up][j_up];
        float gf = g_sm[e_up][j_up + 64];
        float gg = g_sm[e_up][j_up + 128];
        float go = g_sm[e_up][j_up + 192];
        c_state = sigf(gf) * c_state + sigf(gi) * tanhf(gg);
        float h = sigf(go) * tanhf(c_state);
        h_sm[e_up][j_up] = h;
        h1_row[s * HDIM] = h;      // coalesced per warp
        __syncthreads();
    }
}

// ---------------------------------------------------------------------------
// Layer 1 + FC: h1[B,T,64] -> out[B,1]
// ---------------------------------------------------------------------------
__global__ void __launch_bounds__(256) lstm_layer1_fc(
    const float* __restrict__ Wih, const float* __restrict__ Whh,
    const float* __restrict__ bih, const float* __restrict__ bhh,
    const float* __restrict__ Wfc, const float* __restrict__ bfc,
    float* __restrict__ out)
{
    __shared__ float in_sm[2][NB][HDIM];  // double-buffered layer-1 input
    __shared__ float h_sm[NB][HDIM];
    __shared__ float g_sm[NB][GDIM];

    const int tid = threadIdx.x;
    const int b0  = blockIdx.x * NB;

    u64 wih[32], whh[32];
    {
        const ulonglong2* ir = (const ulonglong2*)(Wih + tid * HDIM);
        const ulonglong2* hr = (const ulonglong2*)(Whh + tid * HDIM);
#pragma unroll
        for (int i = 0; i < 16; i++) {
            ulonglong2 v = ir[i];
            wih[2 * i] = v.x; wih[2 * i + 1] = v.y;
        }
#pragma unroll
        for (int i = 0; i < 16; i++) {
            ulonglong2 v = hr[i];
            whh[2 * i] = v.x; whh[2 * i + 1] = v.y;
        }
    }
    const float bias = bih[tid] + bhh[tid];
    const int e_up = tid >> 6, j_up = tid & 63;
    const float* h1_row = g_h1 + ((size_t)(b0 + e_up) * T_STEPS) * HDIM + j_up;

    in_sm[0][e_up][j_up] = h1_row[0];   // step-0 input
    ((float*)h_sm)[tid] = 0.0f;
    float c_state = 0.0f;
    __syncthreads();

    for (int s = 0; s < T_STEPS; s++) {
        const int buf = s & 1;
        // prefetch next step's input into a register (hides DRAM/L2 latency)
        float pre_in = 0.0f;
        if (s + 1 < T_STEPS) pre_in = h1_row[(size_t)(s + 1) * HDIM];

        u64 acc[NB];
#pragma unroll
        for (int e = 0; e < NB; e++) {
            u64 a = pk(bias, 0.0f);
            const ulonglong2* xe = (const ulonglong2*)in_sm[buf][e];
            const ulonglong2* he = (const ulonglong2*)h_sm[e];
#pragma unroll
            for (int i = 0; i < 16; i++) {
                ulonglong2 xv = xe[i];
                a = f2(xv.x, wih[2 * i], a);
                a = f2(xv.y, wih[2 * i + 1], a);
            }
#pragma unroll
            for (int i = 0; i < 16; i++) {
                ulonglong2 hv = he[i];
                a = f2(hv.x, whh[2 * i], a);
                a = f2(hv.y, whh[2 * i + 1], a);
            }
            acc[e] = a;
        }
#pragma unroll
        for (int e = 0; e < NB; e++) {
            float lo, hi; upk(acc[e], lo, hi);
            g_sm[e][tid] = lo + hi;
        }
        __syncthreads();

        float gi = g_sm[e_up][j_up];
        float gf = g_sm[e_up][j_up + 64];
        float gg = g_sm[e_up][j_up + 128];
        float go = g_sm[e_up][j_up + 192];
        c_state = sigf(gf) * c_state + sigf(gi) * tanhf(gg);
        float h = sigf(go) * tanhf(c_state);
        h_sm[e_up][j_up] = h;
        in_sm[buf ^ 1][e_up][j_up] = pre_in;
        __syncthreads();
    }

    // Fused FC on the final hidden state: out[b] = h . Wfc + bfc
    float p = h_sm[e_up][j_up] * Wfc[j_up];
#pragma unroll
    for (int o = 16; o > 0; o >>= 1) p += __shfl_xor_sync(0xffffffffu, p, o);
    const int wid = tid >> 5, lid = tid & 31;
    if (lid == 0) g_sm[0][wid] = p;    // 8 warp partials (2 per batch elem)
    __syncthreads();
    if (tid < NB) out[b0 + tid] = g_sm[0][2 * tid] + g_sm[0][2 * tid + 1] + bfc[0];
}

// ---------------------------------------------------------------------------
extern "C" void kernel_launch(void* const* d_in, const int* in_sizes, int n_in,
                              void* d_out, int out_size)
{
    const float* x    = (const float*)d_in[0];
    const float* Wih0 = (const float*)d_in[1];
    const float* Whh0 = (const float*)d_in[2];
    const float* bih0 = (const float*)d_in[3];
    const float* bhh0 = (const float*)d_in[4];
    const float* Wih1 = (const float*)d_in[5];
    const float* Whh1 = (const float*)d_in[6];
    const float* bih1 = (const float*)d_in[7];
    const float* bhh1 = (const float*)d_in[8];
    const float* Wfc  = (const float*)d_in[9];
    const float* bfc  = (const float*)d_in[10];
    float* out = (float*)d_out;

    dim3 grid(B_TOTAL / NB), block(256);
    lstm_layer0<<<grid, block>>>(x, Wih0, Whh0, bih0, bhh0);
    lstm_layer1_fc<<<grid, block>>>(Wih1, Whh1, bih1, bhh1, Wfc, bfc, out);
}

// round 4
// speedup vs baseline: 1.3207x; 1.3207x over previous
#include <cuda_runtime.h>

// 2-layer LSTM (B=4096, T=256, D=4, H=64) + FC, fp32.
// Register-tiled shared-memory GEMM per timestep:
//   - weights (128KB) live in smem, XOR-swizzled per 16B chunk for
//     conflict-free broadcast wavefronts
//   - thread tile = 4 gates x 4 elems, 16 packed f32x2 accumulators
//   - fma.rn.f32x2 everywhere (2x fp32 MAC rate)
//   - 512 threads/CTA, 32 batch elems/CTA, grid=128 (single wave)
//   - double-buffered [input ; h] vector rows in smem; global prefetch of
//     next-step input overlapped with the GEMM phase

#define TT    256
#define HD    64
#define GD    256
#define EC    32          // batch elems per CTA
#define NT    512
#define ROWB  512         // bytes per smem row (32 chunks x 16B)
#define V_OFF 131072
#define VBUF  16384       // one v buffer: 32 rows x 512B
#define G_OFF 163840
#define SM_TOTAL 196608

typedef unsigned long long u64;

__device__ float g_h1[(size_t)4096 * TT * HD];   // layer0 output scratch

static __device__ __forceinline__ u64 pk2(float lo, float hi) {
    u64 r; asm("mov.b64 %0,{%1,%2};" : "=l"(r) : "f"(lo), "f"(hi)); return r;
}
static __device__ __forceinline__ void up2(u64 v, float& lo, float& hi) {
    asm("mov.b64 {%0,%1},%2;" : "=f"(lo), "=f"(hi) : "l"(v));
}
static __device__ __forceinline__ u64 f2(u64 a, u64 b, u64 c) {
    u64 d; asm("fma.rn.f32x2 %0,%1,%2,%3;" : "=l"(d) : "l"(a), "l"(b), "l"(c));
    return d;
}
static __device__ __forceinline__ float sigf(float x) {
    return __fdividef(1.f, 1.f + __expf(-x));
}
static __device__ __forceinline__ float tanhfast(float x) {
    return __fdividef(2.f, 1.f + __expf(-2.f * x)) - 1.f;
}

// one 4-k chunk: 8 LDS.128 -> 32 FFMA2  (acc[4 gates][4 elems], k-pair packed)
#define GEMM_CHUNK(AOFF)                                                      \
    do {                                                                      \
        ulonglong2 w0 = wp[b][(AOFF)];                                        \
        ulonglong2 w1 = wp[b][32 + (AOFF)];                                   \
        ulonglong2 w2 = wp[b][64 + (AOFF)];                                   \
        ulonglong2 w3 = wp[b][96 + (AOFF)];                                   \
        ulonglong2 x0 = vp[b][(AOFF)];                                        \
        ulonglong2 x1 = vp[b][32 + (AOFF)];                                   \
        ulonglong2 x2 = vp[b][64 + (AOFF)];                                   \
        ulonglong2 x3 = vp[b][96 + (AOFF)];                                   \
        acc[0][0] = f2(w0.x, x0.x, acc[0][0]); acc[0][0] = f2(w0.y, x0.y, acc[0][0]); \
        acc[0][1] = f2(w0.x, x1.x, acc[0][1]); acc[0][1] = f2(w0.y, x1.y, acc[0][1]); \
        acc[0][2] = f2(w0.x, x2.x, acc[0][2]); acc[0][2] = f2(w0.y, x2.y, acc[0][2]); \
        acc[0][3] = f2(w0.x, x3.x, acc[0][3]); acc[0][3] = f2(w0.y, x3.y, acc[0][3]); \
        acc[1][0] = f2(w1.x, x0.x, acc[1][0]); acc[1][0] = f2(w1.y, x0.y, acc[1][0]); \
        acc[1][1] = f2(w1.x, x1.x, acc[1][1]); acc[1][1] = f2(w1.y, x1.y, acc[1][1]); \
        acc[1][2] = f2(w1.x, x2.x, acc[1][2]); acc[1][2] = f2(w1.y, x2.y, acc[1][2]); \
        acc[1][3] = f2(w1.x, x3.x, acc[1][3]); acc[1][3] = f2(w1.y, x3.y, acc[1][3]); \
        acc[2][0] = f2(w2.x, x0.x, acc[2][0]); acc[2][0] = f2(w2.y, x0.y, acc[2][0]); \
        acc[2][1] = f2(w2.x, x1.x, acc[2][1]); acc[2][1] = f2(w2.y, x1.y, acc[2][1]); \
        acc[2][2] = f2(w2.x, x2.x, acc[2][2]); acc[2][2] = f2(w2.y, x2.y, acc[2][2]); \
        acc[2][3] = f2(w2.x, x3.x, acc[2][3]); acc[2][3] = f2(w2.y, x3.y, acc[2][3]); \
        acc[3][0] = f2(w3.x, x0.x, acc[3][0]); acc[3][0] = f2(w3.y, x0.y, acc[3][0]); \
        acc[3][1] = f2(w3.x, x1.x, acc[3][1]); acc[3][1] = f2(w3.y, x1.y, acc[3][1]); \
        acc[3][2] = f2(w3.x, x2.x, acc[3][2]); acc[3][2] = f2(w3.y, x2.y, acc[3][2]); \
        acc[3][3] = f2(w3.x, x3.x, acc[3][3]); acc[3][3] = f2(w3.y, x3.y, acc[3][3]); \
    } while (0)

#define GATE_STORE()                                                          \
    do {                                                                      \
        _Pragma("unroll")                                                     \
        for (int ei = 0; ei < 4; ei++) {                                      \
            float lo, hi; float4 r;                                           \
            up2(acc[0][ei], lo, hi); r.x = lo + hi;                           \
            up2(acc[1][ei], lo, hi); r.y = lo + hi;                           \
            up2(acc[2][ei], lo, hi); r.z = lo + hi;                           \
            up2(acc[3][ei], lo, hi); r.w = lo + hi;                           \
            *(float4*)(sm + G_OFF + (e0 + ei) * 1024 + g0 * 4) = r;           \
        }                                                                     \
    } while (0)

// ---------------------------------------------------------------------------
// Layer 1 + FC
// ---------------------------------------------------------------------------
__global__ void __launch_bounds__(NT, 1) lstm_l1(
    const float* __restrict__ Wih, const float* __restrict__ Whh,
    const float* __restrict__ bih, const float* __restrict__ bhh,
    const float* __restrict__ Wfc, const float* __restrict__ bfc,
    float* __restrict__ out)
{
    extern __shared__ char sm[];
    const int tid = threadIdx.x;
    const int b0  = blockIdx.x * EC;
    const int w   = tid >> 5, l = tid & 31;
    const int gb  = (w & 7) * 8 + (l & 7);
    const int eb  = (w >> 3) * 4 + ((l >> 3) & 3);
    const int g0  = gb * 4, e0 = eb * 4;
    const int swW = gb & 7, swV = eb & 7;

    // fill weights into smem, XOR-swizzled per chunk (row = [Wih row ; Whh row])
    for (int i = tid; i < GD * 32; i += NT) {
        int g = i >> 5, kc = i & 31, k = kc * 4;
        const float* src = (k < HD) ? (Wih + g * HD + k) : (Whh + g * HD + (k - HD));
        float4 v = *(const float4*)src;
        int phys = kc ^ ((g >> 2) & 7);
        *(float4*)(sm + g * ROWB + phys * 16) = v;
    }

    // update-role mapping: thread -> (elem ue, hidden j uj..uj+3)
    const int ue  = tid >> 4;
    const int uj  = (tid & 15) << 2;
    const int swU = (ue >> 2) & 7;
    const float* h1p = g_h1 + ((size_t)(b0 + ue) * TT) * HD + uj;

    // initial v buffer 0: input = h1(t=0), h = 0
    {
        float4 h10 = *(const float4*)h1p;
        *(float4*)(sm + V_OFF + ue * ROWB + (((uj >> 2) ^ swU) << 4)) = h10;
        *(float4*)(sm + V_OFF + ue * ROWB + (((16 + (uj >> 2)) ^ swU) << 4)) =
            make_float4(0.f, 0.f, 0.f, 0.f);
    }

    float bias[4];
#pragma unroll
    for (int gi = 0; gi < 4; gi++) bias[gi] = bih[g0 + gi] + bhh[g0 + gi];
    const float4 wfc = *(const float4*)(Wfc + uj);
    const float bfc0 = bfc[0];

    const ulonglong2* wp[8];
    const ulonglong2* vp[8];
#pragma unroll
    for (int b = 0; b < 8; b++) {
        wp[b] = (const ulonglong2*)(sm + g0 * ROWB + ((b ^ swW) << 4));
        vp[b] = (const ulonglong2*)(sm + V_OFF + e0 * ROWB + ((b ^ swV) << 4));
    }
    char* vwr  = sm + V_OFF + VBUF + ue * ROWB;   // update writes -> next buffer
    int vflip  = VBUF / 16;                        // ulonglong2 elems per buffer
    int wrflip = -VBUF;
    const int ph_h  = ((16 + (uj >> 2)) ^ swU) << 4;
    const int ph_in = ((uj >> 2) ^ swU) << 4;

    float c0 = 0.f, c1 = 0.f, c2 = 0.f, c3 = 0.f;
    float hh0 = 0.f, hh1 = 0.f, hh2 = 0.f, hh3 = 0.f;
    __syncthreads();

    for (int s = 0; s < TT; s++) {
        float4 pin = make_float4(0.f, 0.f, 0.f, 0.f);
        if (s + 1 < TT) pin = *(const float4*)(h1p + (size_t)(s + 1) * HD);

        u64 acc[4][4];
#pragma unroll
        for (int gi = 0; gi < 4; gi++)
#pragma unroll
            for (int ei = 0; ei < 4; ei++) acc[gi][ei] = pk2(bias[gi], 0.f);

#pragma unroll
        for (int a = 0; a < 4; a++)
#pragma unroll
            for (int b = 0; b < 8; b++) GEMM_CHUNK(a * 8);

        GATE_STORE();
        __syncthreads();

        const float4* gp = (const float4*)(sm + G_OFF + ue * 1024);
        float4 gi4 = gp[uj >> 2];
        float4 gf4 = gp[16 + (uj >> 2)];
        float4 gg4 = gp[32 + (uj >> 2)];
        float4 go4 = gp[48 + (uj >> 2)];
        c0 = sigf(gf4.x) * c0 + sigf(gi4.x) * tanhfast(gg4.x);
        c1 = sigf(gf4.y) * c1 + sigf(gi4.y) * tanhfast(gg4.y);
        c2 = sigf(gf4.z) * c2 + sigf(gi4.z) * tanhfast(gg4.z);
        c3 = sigf(gf4.w) * c3 + sigf(gi4.w) * tanhfast(gg4.w);
        hh0 = sigf(go4.x) * tanhfast(c0);
        hh1 = sigf(go4.y) * tanhfast(c1);
        hh2 = sigf(go4.z) * tanhfast(c2);
        hh3 = sigf(go4.w) * tanhfast(c3);
        *(float4*)(vwr + ph_h)  = make_float4(hh0, hh1, hh2, hh3);
        *(float4*)(vwr + ph_in) = pin;
        __syncthreads();

#pragma unroll
        for (int b = 0; b < 8; b++) vp[b] += vflip;
        vwr += wrflip;
        vflip = -vflip; wrflip = -wrflip;
    }

    // fused FC on final hidden state
    float p = hh0 * wfc.x + hh1 * wfc.y + hh2 * wfc.z + hh3 * wfc.w;
    p += __shfl_xor_sync(0xffffffffu, p, 8);
    p += __shfl_xor_sync(0xffffffffu, p, 4);
    p += __shfl_xor_sync(0xffffffffu, p, 2);
    p += __shfl_xor_sync(0xffffffffu, p, 1);
    if ((tid & 15) == 0) out[b0 + ue] = p + bfc0;
}

// ---------------------------------------------------------------------------
// Layer 0: x[B,T,4] -> h1 scratch.  K = 4 (x) + 64 (h) = 17 chunks.
// ---------------------------------------------------------------------------
__global__ void __launch_bounds__(NT, 1) lstm_l0(
    const float* __restrict__ x, const float* __restrict__ Wih,
    const float* __restrict__ Whh, const float* __restrict__ bih,
    const float* __restrict__ bhh)
{
    extern __shared__ char sm[];
    const int tid = threadIdx.x;
    const int b0  = blockIdx.x * EC;
    const int w   = tid >> 5, l = tid & 31;
    const int gb  = (w & 7) * 8 + (l & 7);
    const int eb  = (w >> 3) * 4 + ((l >> 3) & 3);
    const int g0  = gb * 4, e0 = eb * 4;
    const int swW = gb & 7, swV = eb & 7;

    // weights: row = [Wih0 row (4) ; Whh0 row (64)] -> chunks 0..16
    for (int i = tid; i < GD * 32; i += NT) {
        int g = i >> 5, kc = i & 31;
        if (kc < 17) {
            float4 v;
            if (kc == 0) v = *(const float4*)(Wih + g * 4);
            else         v = *(const float4*)(Whh + g * HD + (kc * 4 - 4));
            int phys = kc ^ ((g >> 2) & 7);
            *(float4*)(sm + g * ROWB + phys * 16) = v;
        }
    }

    const int ue  = tid >> 4;
    const int uj  = (tid & 15) << 2;
    const int swU = (ue >> 2) & 7;
    float* h1w = g_h1 + ((size_t)(b0 + ue) * TT) * HD + uj;

    // initial v buffer 0: h = 0 (chunks 1..16); x(0) into chunk 0
    *(float4*)(sm + V_OFF + ue * ROWB + (((1 + (uj >> 2)) ^ swU) << 4)) =
        make_float4(0.f, 0.f, 0.f, 0.f);
    const float* xp = 0;
    if (tid < 32) {
        xp = x + (size_t)(b0 + tid) * TT * 4;
        float4 x0 = *(const float4*)xp;
        *(float4*)(sm + V_OFF + tid * ROWB + (((tid >> 2) & 7) << 4)) = x0;
    }

    float bias[4];
#pragma unroll
    for (int gi = 0; gi < 4; gi++) bias[gi] = bih[g0 + gi] + bhh[g0 + gi];

    const ulonglong2* wp[8];
    const ulonglong2* vp[8];
#pragma unroll
    for (int b = 0; b < 8; b++) {
        wp[b] = (const ulonglong2*)(sm + g0 * ROWB + ((b ^ swW) << 4));
        vp[b] = (const ulonglong2*)(sm + V_OFF + e0 * ROWB + ((b ^ swV) << 4));
    }
    char* vwr  = sm + V_OFF + VBUF + ue * ROWB;
    char* xwr  = sm + V_OFF + VBUF + (tid & 31) * ROWB;  // only tid<32 uses
    int vflip  = VBUF / 16;
    int wrflip = -VBUF;
    const int ph_h = ((1 + (uj >> 2)) ^ swU) << 4;
    const int ph_x = (((tid >> 2) & 7)) << 4;            // chunk 0 ^ swizzle(e=tid)

    float c0 = 0.f, c1 = 0.f, c2 = 0.f, c3 = 0.f;
    __syncthreads();

    for (int s = 0; s < TT; s++) {
        float4 pinx = make_float4(0.f, 0.f, 0.f, 0.f);
        if (tid < 32 && s + 1 < TT)
            pinx = *(const float4*)(xp + (size_t)(s + 1) * 4);

        u64 acc[4][4];
#pragma unroll
        for (int gi = 0; gi < 4; gi++)
#pragma unroll
            for (int ei = 0; ei < 4; ei++) acc[gi][ei] = pk2(bias[gi], 0.f);

#pragma unroll
        for (int a = 0; a < 2; a++)
#pragma unroll
            for (int b = 0; b < 8; b++) GEMM_CHUNK(a * 8);
        { int b = 0; GEMM_CHUNK(16); }   // chunk kc=16 (a=2, b=0)

        GATE_STORE();
        __syncthreads();

        const float4* gp = (const float4*)(sm + G_OFF + ue * 1024);
        float4 gi4 = gp[uj >> 2];
        float4 gf4 = gp[16 + (uj >> 2)];
        float4 gg4 = gp[32 + (uj >> 2)];
        float4 go4 = gp[48 + (uj >> 2)];
        c0 = sigf(gf4.x) * c0 + sigf(gi4.x) * tanhfast(gg4.x);
        c1 = sigf(gf4.y) * c1 + sigf(gi4.y) * tanhfast(gg4.y);
        c2 = sigf(gf4.z) * c2 + sigf(gi4.z) * tanhfast(gg4.z);
        c3 = sigf(gf4.w) * c3 + sigf(gi4.w) * tanhfast(gg4.w);
        float h0 = sigf(go4.x) * tanhfast(c0);
        float h1 = sigf(go4.y) * tanhfast(c1);
        float h2 = sigf(go4.z) * tanhfast(c2);
        float h3 = sigf(go4.w) * tanhfast(c3);
        float4 hv = make_float4(h0, h1, h2, h3);
        *(float4*)(vwr + ph_h) = hv;
        *(float4*)(h1w + (size_t)s * HD) = hv;            // h1 to global
        if (tid < 32) *(float4*)(xwr + ph_x) = pinx;      // x(t+1)
        __syncthreads();

#pragma unroll
        for (int b = 0; b < 8; b++) vp[b] += vflip;
        vwr += wrflip; xwr += wrflip;
        vflip = -vflip; wrflip = -wrflip;
    }
}

// ---------------------------------------------------------------------------
extern "C" void kernel_launch(void* const* d_in, const int* in_sizes, int n_in,
                              void* d_out, int out_size)
{
    const float* x    = (const float*)d_in[0];
    const float* Wih0 = (const float*)d_in[1];
    const float* Whh0 = (const float*)d_in[2];
    const float* bih0 = (const float*)d_in[3];
    const float* bhh0 = (const float*)d_in[4];
    const float* Wih1 = (const float*)d_in[5];
    const float* Whh1 = (const float*)d_in[6];
    const float* bih1 = (const float*)d_in[7];
    const float* bhh1 = (const float*)d_in[8];
    const float* Wfc  = (const float*)d_in[9];
    const float* bfc  = (const float*)d_in[10];
    float* out = (float*)d_out;

    cudaFuncSetAttribute(lstm_l0, cudaFuncAttributeMaxDynamicSharedMemorySize, SM_TOTAL);
    cudaFuncSetAttribute(lstm_l1, cudaFuncAttributeMaxDynamicSharedMemorySize, SM_TOTAL);

    dim3 grid(4096 / EC), block(NT);
    lstm_l0<<<grid, block, SM_TOTAL>>>(x, Wih0, Whh0, bih0, bhh0);
    lstm_l1<<<grid, block, SM_TOTAL>>>(Wih1, Whh1, bih1, bhh1, Wfc, bfc, out);
}

// round 5
// speedup vs baseline: 1.4289x; 1.0819x over previous
#include <cuda_runtime.h>

// 2-layer LSTM (B=4096, T=256, D=4, H=64) + FC, fp32.
// Register-tiled smem GEMM per timestep with FUSED cell update:
//   - thread's 4 gate rows = {j, j+64, j+128, j+192} = (i,f,g,o) of hidden
//     unit j  ->  cell update happens in-register, no gate smem round trip,
//     ONE __syncthreads per timestep.
//   - weights (<=128KB) in smem, XOR-swizzled (g&7) per 16B chunk for
//     conflict-free broadcast wavefronts; fma.rn.f32x2 throughout.
//   - activations via MUFU tanh.approx: sig(x)=0.5*tanh(0.5x)+0.5.
//   - 512 threads/CTA, 32 batch elems/CTA, grid=128 (single wave).

#define TT    256
#define HD    64
#define GD    256
#define EC    32
#define NT    512
#define ROWB  512         // bytes per smem row (32 chunks x 16B)
#define V_OFF 131072
#define VBUF  16384       // one v buffer: 32 rows x 512B
#define SM_TOTAL 196608   // weights 128K + 2 v buffers 32K (+ slack)

typedef unsigned long long u64;

__device__ float g_h1[(size_t)4096 * TT * HD];   // layer0 output scratch

static __device__ __forceinline__ u64 pk2(float lo, float hi) {
    u64 r; asm("mov.b64 %0,{%1,%2};" : "=l"(r) : "f"(lo), "f"(hi)); return r;
}
static __device__ __forceinline__ void up2(u64 v, float& lo, float& hi) {
    asm("mov.b64 {%0,%1},%2;" : "=f"(lo), "=f"(hi) : "l"(v));
}
static __device__ __forceinline__ u64 f2(u64 a, u64 b, u64 c) {
    u64 d; asm("fma.rn.f32x2 %0,%1,%2,%3;" : "=l"(d) : "l"(a), "l"(b), "l"(c));
    return d;
}
static __device__ __forceinline__ float tanha(float x) {
    float r; asm("tanh.approx.f32 %0, %1;" : "=f"(r) : "f"(x)); return r;
}
static __device__ __forceinline__ float sigt(float x) {
    return fmaf(0.5f, tanha(0.5f * x), 0.5f);
}

// one 4-k chunk: 8 LDS.128 -> 32 FFMA2.
// w rows {j, j+64, j+128, j+192} -> u2 offsets {0, 2048, 4096, 6144};
// x rows {e0..e0+3}              -> u2 offsets {0, 32, 64, 96}.
#define GEMM_CHUNK(AOFF)                                                      \
    do {                                                                      \
        ulonglong2 w0 = wp[b][(AOFF)];                                        \
        ulonglong2 w1 = wp[b][2048 + (AOFF)];                                 \
        ulonglong2 w2 = wp[b][4096 + (AOFF)];                                 \
        ulonglong2 w3 = wp[b][6144 + (AOFF)];                                 \
        ulonglong2 x0 = vp[b][(AOFF)];                                        \
        ulonglong2 x1 = vp[b][32 + (AOFF)];                                   \
        ulonglong2 x2 = vp[b][64 + (AOFF)];                                   \
        ulonglong2 x3 = vp[b][96 + (AOFF)];                                   \
        acc[0][0] = f2(w0.x, x0.x, acc[0][0]); acc[0][0] = f2(w0.y, x0.y, acc[0][0]); \
        acc[0][1] = f2(w0.x, x1.x, acc[0][1]); acc[0][1] = f2(w0.y, x1.y, acc[0][1]); \
        acc[0][2] = f2(w0.x, x2.x, acc[0][2]); acc[0][2] = f2(w0.y, x2.y, acc[0][2]); \
        acc[0][3] = f2(w0.x, x3.x, acc[0][3]); acc[0][3] = f2(w0.y, x3.y, acc[0][3]); \
        acc[1][0] = f2(w1.x, x0.x, acc[1][0]); acc[1][0] = f2(w1.y, x0.y, acc[1][0]); \
        acc[1][1] = f2(w1.x, x1.x, acc[1][1]); acc[1][1] = f2(w1.y, x1.y, acc[1][1]); \
        acc[1][2] = f2(w1.x, x2.x, acc[1][2]); acc[1][2] = f2(w1.y, x2.y, acc[1][2]); \
        acc[1][3] = f2(w1.x, x3.x, acc[1][3]); acc[1][3] = f2(w1.y, x3.y, acc[1][3]); \
        acc[2][0] = f2(w2.x, x0.x, acc[2][0]); acc[2][0] = f2(w2.y, x0.y, acc[2][0]); \
        acc[2][1] = f2(w2.x, x1.x, acc[2][1]); acc[2][1] = f2(w2.y, x1.y, acc[2][1]); \
        acc[2][2] = f2(w2.x, x2.x, acc[2][2]); acc[2][2] = f2(w2.y, x2.y, acc[2][2]); \
        acc[2][3] = f2(w2.x, x3.x, acc[2][3]); acc[2][3] = f2(w2.y, x3.y, acc[2][3]); \
        acc[3][0] = f2(w3.x, x0.x, acc[3][0]); acc[3][0] = f2(w3.y, x0.y, acc[3][0]); \
        acc[3][1] = f2(w3.x, x1.x, acc[3][1]); acc[3][1] = f2(w3.y, x1.y, acc[3][1]); \
        acc[3][2] = f2(w3.x, x2.x, acc[3][2]); acc[3][2] = f2(w3.y, x2.y, acc[3][2]); \
        acc[3][3] = f2(w3.x, x3.x, acc[3][3]); acc[3][3] = f2(w3.y, x3.y, acc[3][3]); \
    } while (0)

#define ACC_INIT()                                                            \
    do {                                                                      \
        _Pragma("unroll")                                                     \
        for (int gi = 0; gi < 4; gi++)                                        \
            _Pragma("unroll")                                                 \
            for (int ei = 0; ei < 4; ei++) acc[gi][ei] = pk2(bias[gi], 0.f);  \
    } while (0)

// fused update for elem slot ei: gates -> c (register) -> h
#define UPDATE_EI(ei, HOUT)                                                   \
    do {                                                                      \
        float glo, ghi, vi, vf, vg, vo;                                       \
        up2(acc[0][ei], glo, ghi); vi = glo + ghi;                            \
        up2(acc[1][ei], glo, ghi); vf = glo + ghi;                            \
        up2(acc[2][ei], glo, ghi); vg = glo + ghi;                            \
        up2(acc[3][ei], glo, ghi); vo = glo + ghi;                            \
        c[ei] = sigt(vf) * c[ei] + sigt(vi) * tanha(vg);                      \
        HOUT = sigt(vo) * tanha(c[ei]);                                       \
    } while (0)

// ---------------------------------------------------------------------------
// Layer 1 + FC
// ---------------------------------------------------------------------------
__global__ void __launch_bounds__(NT, 1) lstm_l1(
    const float* __restrict__ Wih, const float* __restrict__ Whh,
    const float* __restrict__ bih, const float* __restrict__ bhh,
    const float* __restrict__ Wfc, const float* __restrict__ bfc,
    float* __restrict__ out)
{
    extern __shared__ char sm[];
    const int tid = threadIdx.x;
    const int b0  = blockIdx.x * EC;
    const int w   = tid >> 5, l = tid & 31;
    const int j   = (w & 7) * 8 + (l & 7);            // hidden unit (gate quartet)
    const int eb  = (w >> 3) * 4 + ((l >> 3) & 3);
    const int e0  = eb * 4;
    const int swW = j & 7, swV = eb & 7;

    // weights into smem: row = [Wih row (64) ; Whh row (64)], swizzle kc^(g&7)
    for (int i = tid; i < GD * 32; i += NT) {
        int g = i >> 5, kc = i & 31, k = kc * 4;
        const float* src = (k < HD) ? (Wih + g * HD + k) : (Whh + g * HD + (k - HD));
        float4 v = *(const float4*)src;
        *(float4*)(sm + g * ROWB + ((kc ^ (g & 7)) << 4)) = v;
    }

    // prefetch-role mapping (writes next step's input vector)
    const int ue  = tid >> 4;
    const int uj  = (tid & 15) << 2;
    const int swU = (ue >> 2) & 7;
    const float* h1p = g_h1 + ((size_t)(b0 + ue) * TT) * HD + uj;

    // initial v buffer 0: input = h1(t=0), h = 0
    {
        float4 h10 = *(const float4*)h1p;
        *(float4*)(sm + V_OFF + ue * ROWB + (((uj >> 2) ^ swU) << 4)) = h10;
        *(float4*)(sm + V_OFF + ue * ROWB + (((16 + (uj >> 2)) ^ swU) << 4)) =
            make_float4(0.f, 0.f, 0.f, 0.f);
    }

    float bias[4];
#pragma unroll
    for (int gi = 0; gi < 4; gi++) bias[gi] = bih[j + 64 * gi] + bhh[j + 64 * gi];

    const ulonglong2* wp[8];
    const ulonglong2* vp[8];
#pragma unroll
    for (int b = 0; b < 8; b++) {
        wp[b] = (const ulonglong2*)(sm + j * ROWB + ((b ^ swW) << 4));
        vp[b] = (const ulonglong2*)(sm + V_OFF + e0 * ROWB + ((b ^ swV) << 4));
    }
    // h writes: column of unit j inside rows e0..e0+3 of the write buffer
    const int colH = ((((16 + (j >> 2)) ^ swV) << 4)) + ((j & 3) << 2);
    char* hw = sm + V_OFF + VBUF + e0 * ROWB + colH;
    char* pw = sm + V_OFF + VBUF + ue * ROWB + (((uj >> 2) ^ swU) << 4);
    int vflip = VBUF / 16, wrflip = -VBUF;

    float c[4] = {0.f, 0.f, 0.f, 0.f};
    __syncthreads();

    for (int s = 0; s < TT; s++) {
        float4 pin = make_float4(0.f, 0.f, 0.f, 0.f);
        if (s + 1 < TT) pin = *(const float4*)(h1p + (size_t)(s + 1) * HD);

        u64 acc[4][4];
        ACC_INIT();
#pragma unroll
        for (int a = 0; a < 4; a++)
#pragma unroll
            for (int b = 0; b < 8; b++) GEMM_CHUNK(a * 8);

        float h0, h1v, h2, h3;
        UPDATE_EI(0, h0); UPDATE_EI(1, h1v); UPDATE_EI(2, h2); UPDATE_EI(3, h3);
        *(float*)(hw)            = h0;
        *(float*)(hw + ROWB)     = h1v;
        *(float*)(hw + 2 * ROWB) = h2;
        *(float*)(hw + 3 * ROWB) = h3;
        *(float4*)pw = pin;
        __syncthreads();

#pragma unroll
        for (int b = 0; b < 8; b++) vp[b] += vflip;
        hw += wrflip; pw += wrflip;
        vflip = -vflip; wrflip = -wrflip;
    }

    // final h (t=TT-1) landed in buffer 0 (V_OFF). Fused FC.
    float4 hf = *(const float4*)(sm + V_OFF + ue * ROWB +
                                 (((16 + (uj >> 2)) ^ swU) << 4));
    const float4 wfc = *(const float4*)(Wfc + uj);
    float p = hf.x * wfc.x + hf.y * wfc.y + hf.z * wfc.z + hf.w * wfc.w;
    p += __shfl_xor_sync(0xffffffffu, p, 8);
    p += __shfl_xor_sync(0xffffffffu, p, 4);
    p += __shfl_xor_sync(0xffffffffu, p, 2);
    p += __shfl_xor_sync(0xffffffffu, p, 1);
    if ((tid & 15) == 0) out[b0 + ue] = p + bfc[0];
}

// ---------------------------------------------------------------------------
// Layer 0: x[B,T,4] -> h1 scratch.  K = 4 (x, chunk 0) + 64 (h, chunks 1..16)
// ---------------------------------------------------------------------------
__global__ void __launch_bounds__(NT, 1) lstm_l0(
    const float* __restrict__ x, const float* __restrict__ Wih,
    const float* __restrict__ Whh, const float* __restrict__ bih,
    const float* __restrict__ bhh)
{
    extern __shared__ char sm[];
    const int tid = threadIdx.x;
    const int b0  = blockIdx.x * EC;
    const int w   = tid >> 5, l = tid & 31;
    const int j   = (w & 7) * 8 + (l & 7);
    const int eb  = (w >> 3) * 4 + ((l >> 3) & 3);
    const int e0  = eb * 4;
    const int swW = j & 7, swV = eb & 7;

    for (int i = tid; i < GD * 32; i += NT) {
        int g = i >> 5, kc = i & 31;
        if (kc < 17) {
            float4 v;
            if (kc == 0) v = *(const float4*)(Wih + g * 4);
            else         v = *(const float4*)(Whh + g * HD + (kc * 4 - 4));
            *(float4*)(sm + g * ROWB + ((kc ^ (g & 7)) << 4)) = v;
        }
    }

    // zero-fill h part of v buffer 0 (chunks 1..16), role (ue, uj)
    const int ue  = tid >> 4;
    const int uj  = (tid & 15) << 2;
    const int swU = (ue >> 2) & 7;
    *(float4*)(sm + V_OFF + ue * ROWB + (((1 + (uj >> 2)) ^ swU) << 4)) =
        make_float4(0.f, 0.f, 0.f, 0.f);
    // x(0) into chunk 0 (tid<32: one elem per thread, full D=4 input)
    const float* xp = 0;
    if (tid < 32) {
        xp = x + (size_t)(b0 + tid) * TT * 4;
        *(float4*)(sm + V_OFF + tid * ROWB + (((tid >> 2) & 7) << 4)) =
            *(const float4*)xp;
    }

    float bias[4];
#pragma unroll
    for (int gi = 0; gi < 4; gi++) bias[gi] = bih[j + 64 * gi] + bhh[j + 64 * gi];

    const ulonglong2* wp[8];
    const ulonglong2* vp[8];
#pragma unroll
    for (int b = 0; b < 8; b++) {
        wp[b] = (const ulonglong2*)(sm + j * ROWB + ((b ^ swW) << 4));
        vp[b] = (const ulonglong2*)(sm + V_OFF + e0 * ROWB + ((b ^ swV) << 4));
    }
    const int colH = ((((1 + (j >> 2)) ^ swV) << 4)) + ((j & 3) << 2);
    char* hw  = sm + V_OFF + VBUF + e0 * ROWB + colH;
    char* xwr = sm + V_OFF + VBUF + (tid & 31) * ROWB + ((((tid >> 2) & 7)) << 4);
    int vflip = VBUF / 16, wrflip = -VBUF;

    // global h1 writes: unit j of elems e0..e0+3
    float* h1w = g_h1 + ((size_t)(b0 + e0) * TT) * HD + j;

    float c[4] = {0.f, 0.f, 0.f, 0.f};
    __syncthreads();

    for (int s = 0; s < TT; s++) {
        float4 pinx = make_float4(0.f, 0.f, 0.f, 0.f);
        if (tid < 32 && s + 1 < TT)
            pinx = *(const float4*)(xp + (size_t)(s + 1) * 4);

        u64 acc[4][4];
        ACC_INIT();
#pragma unroll
        for (int a = 0; a < 2; a++)
#pragma unroll
            for (int b = 0; b < 8; b++) GEMM_CHUNK(a * 8);
        { int b = 0; GEMM_CHUNK(16); }   // chunk kc=16

        float h0, h1v, h2, h3;
        UPDATE_EI(0, h0); UPDATE_EI(1, h1v); UPDATE_EI(2, h2); UPDATE_EI(3, h3);
        *(float*)(hw)            = h0;
        *(float*)(hw + ROWB)     = h1v;
        *(float*)(hw + 2 * ROWB) = h2;
        *(float*)(hw + 3 * ROWB) = h3;
        h1w[(size_t)s * HD]                      = h0;
        h1w[(size_t)s * HD + (size_t)TT * HD]    = h1v;
        h1w[(size_t)s * HD + (size_t)2 * TT * HD] = h2;
        h1w[(size_t)s * HD + (size_t)3 * TT * HD] = h3;
        if (tid < 32) *(float4*)xwr = pinx;
        __syncthreads();

#pragma unroll
        for (int b = 0; b < 8; b++) vp[b] += vflip;
        hw += wrflip; xwr += wrflip;
        vflip = -vflip; wrflip = -wrflip;
    }
}

// ---------------------------------------------------------------------------
extern "C" void kernel_launch(void* const* d_in, const int* in_sizes, int n_in,
                              void* d_out, int out_size)
{
    const float* x    = (const float*)d_in[0];
    const float* Wih0 = (const float*)d_in[1];
    const float* Whh0 = (const float*)d_in[2];
    const float* bih0 = (const float*)d_in[3];
    const float* bhh0 = (const float*)d_in[4];
    const float* Wih1 = (const float*)d_in[5];
    const float* Whh1 = (const float*)d_in[6];
    const float* bih1 = (const float*)d_in[7];
    const float* bhh1 = (const float*)d_in[8];
    const float* Wfc  = (const float*)d_in[9];
    const float* bfc  = (const float*)d_in[10];
    float* out = (float*)d_out;

    cudaFuncSetAttribute(lstm_l0, cudaFuncAttributeMaxDynamicSharedMemorySize, SM_TOTAL);
    cudaFuncSetAttribute(lstm_l1, cudaFuncAttributeMaxDynamicSharedMemorySize, SM_TOTAL);

    dim3 grid(4096 / EC), block(NT);
    lstm_l0<<<grid, block, SM_TOTAL>>>(x, Wih0, Whh0, bih0, bhh0);
    lstm_l1<<<grid, block, SM_TOTAL>>>(Wih1, Whh1, bih1, bhh1, Wfc, bfc, out);
}